// round 11
// baseline (speedup 1.0000x reference)
#include <cuda_runtime.h>
#include <cuda_bf16.h>

// Problem constants (match reference_code)
#define N_L   90
#define N_B   20
#define N_MU  46
#define N_LF  51
#define N_OUTK (N_LF - N_MU + 1)          // 6
#define NBINS (N_L * N_B * N_MU)          // 82800
#define N_LB  (N_L * N_B)                 // 1800
#define NOUT  (N_LB * N_OUTK)             // 10800

#define MN0  (-90.0f)
#define MN1  (-12.0f)
#define MN2  (7.0f)

#define THREADS        256
#define PER_THREAD     8
#define PART_PER_BLOCK (THREADS * PER_THREAD)   // 2048
#define COORD_BYTES    (PART_PER_BLOCK * 3 * 4) // 24576
#define MASS_BYTES     (PART_PER_BLOCK * 4)     // 8192
#define STAGE_BYTES    (COORD_BYTES + MASS_BYTES) // 32768

// conv_zero epilogue shape
#define LB_PER_BLOCK   32                        // 32*46 = 1472 bins/block
#define CONV_THREADS   (LB_PER_BLOCK * N_OUTK)   // 192 active conv threads

// Zero-initialized at module load; re-zeroed by conv_zero_kernel (each block
// zeroes exactly the bin slices it alone consumed). Deterministic per replay.
static __device__ float g_hist[NBINS];

__device__ __forceinline__ int bin_of(float x, float y, float z,
                                      float idx0, float idx1, float idx2) {
    int i0 = __float2int_rn((x - MN0) * idx0);
    int i1 = __float2int_rn((y - MN1) * idx1);
    int i2 = __float2int_rn((z - MN2) * idx2);
    bool ok = (unsigned)i0 < (unsigned)N_L &&
              (unsigned)i1 < (unsigned)N_B &&
              (unsigned)i2 < (unsigned)N_MU;
    return ok ? (i0 * (N_B * N_MU) + i1 * N_MU + i2) : -1;
}

__device__ __forceinline__ void red_add(int b, float m) {
    if (b >= 0) {
        asm volatile("red.global.add.f32 [%0], %1;"
                     :: "l"(&g_hist[b]), "f"(m) : "memory");
    }
}

__device__ __forceinline__ unsigned smem_u32(const void* p) {
    unsigned a;
    asm("{ .reg .u64 t; cvta.to.shared.u64 t, %1; cvt.u32.u64 %0, t; }"
        : "=r"(a) : "l"(p));
    return a;
}

// Histogram: coords+masses staged into smem via cp.async.bulk (TMA bulk path,
// NO LDG/STS wavefronts on the l1tex queue), then the measured-best compute
// phase: stride-3 LDS -> 8 bin computes -> uninterrupted RED burst.
__global__ void __launch_bounds__(THREADS)
hist_kernel(const float* __restrict__ lbm,
            const float* __restrict__ mass,
            int n) {
    __shared__ float sc[PART_PER_BLOCK * 3];   // 24 KB coords
    __shared__ float sm[PART_PER_BLOCK];       //  8 KB masses
    __shared__ __align__(8) unsigned long long mbar;

    const float dx0 = (90.0f - (-90.0f)) / (float)(N_L - 1);
    const float dx1 = (12.0f - (-12.0f)) / (float)(N_B - 1);
    const float dx2 = (16.0f - 7.0f) / (float)(N_MU - 1);
    const float idx0 = 1.0f / dx0;
    const float idx1 = 1.0f / dx1;
    const float idx2 = 1.0f / dx2;

    const int t   = threadIdx.x;
    const int bs  = blockIdx.x * PART_PER_BLOCK;        // block start particle
    const int cnt = min(PART_PER_BLOCK, n - bs);

    if (cnt == PART_PER_BLOCK) {
        const unsigned mbar_a = smem_u32(&mbar);
        const unsigned sc_a   = smem_u32(sc);
        const unsigned sm_a   = smem_u32(sm);
        if (t == 0) {
            asm volatile("mbarrier.init.shared.b64 [%0], 1;" :: "r"(mbar_a) : "memory");
            asm volatile("fence.proxy.async.shared::cta;" ::: "memory");
        }
        __syncthreads();
        if (t == 0) {
            asm volatile("mbarrier.arrive.expect_tx.shared.b64 _, [%0], %1;"
                         :: "r"(mbar_a), "r"((unsigned)STAGE_BYTES) : "memory");
            asm volatile("cp.async.bulk.shared::cta.global.mbarrier::complete_tx::bytes "
                         "[%0], [%1], %2, [%3];"
                         :: "r"(sc_a), "l"(lbm + (size_t)bs * 3),
                            "r"((unsigned)COORD_BYTES), "r"(mbar_a) : "memory");
            asm volatile("cp.async.bulk.shared::cta.global.mbarrier::complete_tx::bytes "
                         "[%0], [%1], %2, [%3];"
                         :: "r"(sm_a), "l"(mass + bs),
                            "r"((unsigned)MASS_BYTES), "r"(mbar_a) : "memory");
        }
        // All threads wait for both bulk copies (acquire orders the smem data).
        for (;;) {
            unsigned ok;
            asm volatile(
                "{\n\t.reg .pred P;\n\t"
                "mbarrier.try_wait.parity.acquire.cta.shared::cta.b64 P, [%1], %2, 0x989680;\n\t"
                "selp.b32 %0, 1, 0, P;\n\t}"
                : "=r"(ok) : "r"(mbar_a), "r"(0u) : "memory");
            if (ok) break;
        }

        int   b[PER_THREAD];
        float m[PER_THREAD];
#pragma unroll
        for (int j = 0; j < PER_THREAD; j++) {
            int p = t + THREADS * j;                    // bank-conflict-free (stride 3)
            b[j] = bin_of(sc[3 * p + 0], sc[3 * p + 1], sc[3 * p + 2],
                          idx0, idx1, idx2);
            m[j] = sm[p];
        }
        // Uninterrupted RED burst.
#pragma unroll
        for (int j = 0; j < PER_THREAD; j++) red_add(b[j], m[j]);
    } else {
        // Tail block: scalar coalesced staging + guarded compute.
        for (int i = t; i < cnt * 3; i += THREADS) sc[i] = lbm[(size_t)bs * 3 + i];
        for (int i = t; i < cnt;     i += THREADS) sm[i] = mass[bs + i];
        __syncthreads();
#pragma unroll
        for (int j = 0; j < PER_THREAD; j++) {
            int p = t + THREADS * j;
            if (p < cnt) {
                int bb = bin_of(sc[3 * p + 0], sc[3 * p + 1], sc[3 * p + 2],
                                idx0, idx1, idx2);
                red_add(bb, sm[p]);
            }
        }
    }
}

// conv+zero epilogue (PDL-launched). Each block owns 32 (l,b) pairs:
// threads 0..191 compute one (lb,k) output each, then the whole block zeroes
// its own 1472-bin slice with coalesced float4 stores.
__global__ void __launch_bounds__(THREADS)
conv_zero_kernel(const float* __restrict__ lf, float* __restrict__ out) {
    __shared__ float s_lf[N_LF];
    int t = threadIdx.x;

    cudaGridDependencySynchronize();

    if (t < N_LF) s_lf[t] = lf[t];
    __syncthreads();

    const int lb0 = blockIdx.x * LB_PER_BLOCK;

    if (t < CONV_THREADS) {
        int lb = lb0 + t / N_OUTK;
        if (lb < N_LB) {
            int k = t % N_OUTK;
            const float* h = &g_hist[lb * N_MU];
            float s = 0.0f;
#pragma unroll
            for (int i = 0; i < N_MU; i++) {
                s = fmaf(h[i], s_lf[k + (N_MU - 1) - i], s);
            }
            out[lb * N_OUTK + k] = s;
        }
    }
    __syncthreads();

    {
        int base_f = lb0 * N_MU;                         // 16B aligned (1472 | base)
        int nf = min(LB_PER_BLOCK * N_MU, NBINS - base_f);
        float4* z4 = (float4*)&g_hist[base_f];
        int n4 = nf / 4;
        for (int i = t; i < n4; i += THREADS) {
            z4[i] = make_float4(0.f, 0.f, 0.f, 0.f);
        }
    }
}

extern "C" void kernel_launch(void* const* d_in, const int* in_sizes, int n_in,
                              void* d_out, int out_size) {
    const float* lbm  = (const float*)d_in[0];   // [N,3] float32
    const float* mass = (const float*)d_in[1];   // [N]   float32
    const float* lf   = (const float*)d_in[2];   // [51]  float32
    float* out = (float*)d_out;                  // [90,20,6] float32

    int n = in_sizes[1];
    int grid = (n + PART_PER_BLOCK - 1) / PART_PER_BLOCK;
    if (grid < 1) grid = 1;

    hist_kernel<<<grid, THREADS>>>(lbm, mass, n);

    {
        cudaLaunchConfig_t cfg = {};
        cfg.gridDim  = dim3((N_LB + LB_PER_BLOCK - 1) / LB_PER_BLOCK, 1, 1);
        cfg.blockDim = dim3(THREADS, 1, 1);
        cfg.dynamicSmemBytes = 0;
        cfg.stream = 0;
        cudaLaunchAttribute attrs[1];
        attrs[0].id = cudaLaunchAttributeProgrammaticStreamSerialization;
        attrs[0].val.programmaticStreamSerializationAllowed = 1;
        cfg.attrs = attrs;
        cfg.numAttrs = 1;
        cudaLaunchKernelEx(&cfg, conv_zero_kernel, lf, out);
    }
}